// round 7
// baseline (speedup 1.0000x reference)
#include <cuda_runtime.h>

#define TT    2048
#define BCOL  8192
#define B4    (BCOL / 4)       // 2048 float4 columns
#define CPB   4                // float4 columns per block
#define SEGS  64               // T-segments per tile
#define SPT   4                // steps per thread (segment length)
#define TILE  (SEGS * SPT)     // 256 T-steps per tile
#define NTILE (TT / TILE)      // 8 tiles
#define NTHR  (SEGS * CPB)     // 256 threads, 8 warps
#define NW    (NTHR / 32)      // 8 warps
#define SEGW  8                // segments per warp
#define GAMMA 0.99f

// Fully fused V-trace (single launch):
//   rho_t = min(1, exp(tl-bl))                              (output)
//   a_t   = v_t + rho_t*(r_t - v_t),  b_t = GAMMA*rho_t     [t==T-1: a=v, b=0]
//   v_t   = a_t + b_t * v_{t+1}   (reverse affine scan)     (output)
// (gamma*v_next cancels exactly in a_t because RHO == CIS == 1.)
//
// Affine maps M(c) = A + P*c; carry flows high-t -> low-t.
// compose(outer, inner): A = A_o + P_o*A_i, P = P_o*P_i.
//
// Per tile: phase-A loads (tl/bl, 8-deep LDG.128 burst) -> rho + store ->
// phase-B loads (v/r, 8-deep burst) -> (a,b) -> intra-warp suffix scan via
// shuffles (3 rounds, barrier-free) -> cross-warp combine through 1 KiB smem
// (sync1) -> carry application (sync2) -> replay + store.
// Two-phase loads cap live input regs at 32 (vs 64 fully batched) so the CTA
// fits 2x per SM; 2 barriers/tile; deterministic; no inter-block comms.
__global__ void __launch_bounds__(NTHR) vtrace_fused(
    const float4* __restrict__ v,  const float4* __restrict__ r,
    const float4* __restrict__ tl, const float4* __restrict__ bl,
    float4* __restrict__ vout, float4* __restrict__ rho_out)
{
    __shared__ float4 sWA[NW][CPB];     // per-warp aggregate A
    __shared__ float4 sWP[NW][CPB];     // per-warp aggregate P
    __shared__ float4 sCarry[CPB];      // carry entering next (lower-t) tile

    const int tid  = threadIdx.x;
    const int col  = tid & (CPB - 1);
    const int seg  = tid >> 2;
    const int wid  = tid >> 5;
    const int sl   = (tid & 31) >> 2;   // segment-local id within warp (0..7)
    const int colg = blockIdx.x * CPB + col;

    if (tid < CPB) sCarry[tid] = make_float4(0.f, 0.f, 0.f, 0.f);
    // First-tile read of sCarry is ordered by sync1 below.

    // Running pointers for this thread's segment in the LAST tile; walk
    // backwards by TILE rows per tile iteration.
    const int base0 = ((NTILE - 1) * TILE + seg * SPT) * B4 + colg;
    const float4* pv  = v       + base0;
    const float4* pr  = r       + base0;
    const float4* ptl = tl      + base0;
    const float4* pbl = bl      + base0;
    float4*       pro = rho_out + base0;
    float4*       pvo = vout    + base0;

    const bool own_last = (seg == SEGS - 1);   // owns t==TT-1 in last tile

    for (int tt = NTILE - 1; tt >= 0; --tt) {
        float4 av[SPT], bv[SPT];
        float4 rv[SPT];                 // rho, live phase A -> phase B

        // ---- phase A: policy loads (8 LDG.128), rho, rho store ----
        {
            float4 t4[SPT], b4[SPT];
            #pragma unroll
            for (int i = 0; i < SPT; ++i) {
                t4[i] = __ldcs(ptl + i * B4);
                b4[i] = __ldcs(pbl + i * B4);
            }
            #pragma unroll
            for (int i = 0; i < SPT; ++i) {
                rv[i].x = fminf(1.f, __expf(t4[i].x - b4[i].x));
                rv[i].y = fminf(1.f, __expf(t4[i].y - b4[i].y));
                rv[i].z = fminf(1.f, __expf(t4[i].z - b4[i].z));
                rv[i].w = fminf(1.f, __expf(t4[i].w - b4[i].w));
                __stcs(pro + i * B4, rv[i]);
            }
        }

        // ---- phase B: value loads (8 LDG.128), build (a, b) ----
        {
            float4 vv[SPT], rr[SPT];
            #pragma unroll
            for (int i = 0; i < SPT; ++i) {
                vv[i] = __ldcs(pv + i * B4);
                rr[i] = __ldcs(pr + i * B4);
            }
            #pragma unroll
            for (int i = 0; i < SPT; ++i) {
                av[i].x = fmaf(rv[i].x, rr[i].x - vv[i].x, vv[i].x);
                av[i].y = fmaf(rv[i].y, rr[i].y - vv[i].y, vv[i].y);
                av[i].z = fmaf(rv[i].z, rr[i].z - vv[i].z, vv[i].z);
                av[i].w = fmaf(rv[i].w, rr[i].w - vv[i].w, vv[i].w);
                bv[i].x = GAMMA * rv[i].x;  bv[i].y = GAMMA * rv[i].y;
                bv[i].z = GAMMA * rv[i].z;  bv[i].w = GAMMA * rv[i].w;
            }
            if (tt == NTILE - 1 && own_last) {     // t==TT-1: a=v, b=0
                av[SPT - 1] = vv[SPT - 1];
                bv[SPT - 1] = make_float4(0.f, 0.f, 0.f, 0.f);
            }
        }

        // ---- per-thread segment aggregate K = M_lo o ... o M_hi ----
        float4 KA = make_float4(0.f, 0.f, 0.f, 0.f);
        float4 KP = make_float4(1.f, 1.f, 1.f, 1.f);
        #pragma unroll
        for (int i = SPT - 1; i >= 0; --i) {
            KA.x = fmaf(bv[i].x, KA.x, av[i].x);
            KA.y = fmaf(bv[i].y, KA.y, av[i].y);
            KA.z = fmaf(bv[i].z, KA.z, av[i].z);
            KA.w = fmaf(bv[i].w, KA.w, av[i].w);
            KP.x *= bv[i].x;  KP.y *= bv[i].y;
            KP.z *= bv[i].z;  KP.w *= bv[i].w;
        }

        // ---- intra-warp suffix scan over 8 segments (shuffles, no BAR) ----
        #pragma unroll
        for (int d = 1; d < SEGW; d <<= 1) {
            const int sh = 4 * d;
            float4 pA, pP;
            pA.x = __shfl_down_sync(0xffffffffu, KA.x, sh);
            pA.y = __shfl_down_sync(0xffffffffu, KA.y, sh);
            pA.z = __shfl_down_sync(0xffffffffu, KA.z, sh);
            pA.w = __shfl_down_sync(0xffffffffu, KA.w, sh);
            pP.x = __shfl_down_sync(0xffffffffu, KP.x, sh);
            pP.y = __shfl_down_sync(0xffffffffu, KP.y, sh);
            pP.z = __shfl_down_sync(0xffffffffu, KP.z, sh);
            pP.w = __shfl_down_sync(0xffffffffu, KP.w, sh);
            if (sl + d < SEGW) {
                KA.x = fmaf(KP.x, pA.x, KA.x);
                KA.y = fmaf(KP.y, pA.y, KA.y);
                KA.z = fmaf(KP.z, pA.z, KA.z);
                KA.w = fmaf(KP.w, pA.w, KA.w);
                KP.x *= pP.x;  KP.y *= pP.y;
                KP.z *= pP.z;  KP.w *= pP.w;
            }
        }

        // nK = suffix aggregate of the segment just above mine (within warp)
        float4 nKA, nKP;
        nKA.x = __shfl_down_sync(0xffffffffu, KA.x, 4);
        nKA.y = __shfl_down_sync(0xffffffffu, KA.y, 4);
        nKA.z = __shfl_down_sync(0xffffffffu, KA.z, 4);
        nKA.w = __shfl_down_sync(0xffffffffu, KA.w, 4);
        nKP.x = __shfl_down_sync(0xffffffffu, KP.x, 4);
        nKP.y = __shfl_down_sync(0xffffffffu, KP.y, 4);
        nKP.z = __shfl_down_sync(0xffffffffu, KP.z, 4);
        nKP.w = __shfl_down_sync(0xffffffffu, KP.w, 4);

        // ---- publish warp aggregates (K at sl==0 spans the whole warp) ----
        if (sl == 0) {
            sWA[wid][col] = KA;
            sWP[wid][col] = KP;
        }
        __syncthreads();    // sync1: aggregates visible; orders sCarry w->r

        // ---- carry entering my warp: C = (W_{wid+1} o..o W_{NW-1})(tc) ----
        float4 C = sCarry[col];
        #pragma unroll
        for (int w2 = NW - 1; w2 >= 1; --w2) {  // innermost (highest t) first
            if (w2 > wid) {
                const float4 A = sWA[w2][col];
                const float4 P = sWP[w2][col];
                C.x = fmaf(P.x, C.x, A.x);
                C.y = fmaf(P.y, C.y, A.y);
                C.z = fmaf(P.z, C.z, A.z);
                C.w = fmaf(P.w, C.w, A.w);
            }
        }

        // ---- carry entering my segment ----
        float4 carry;
        if (sl == SEGW - 1) {
            carry = C;
        } else {
            carry.x = fmaf(nKP.x, C.x, nKA.x);
            carry.y = fmaf(nKP.y, C.y, nKA.y);
            carry.z = fmaf(nKP.z, C.z, nKA.z);
            carry.w = fmaf(nKP.w, C.w, nKA.w);
        }
        __syncthreads();    // sync2: all smem reads done before any rewrite

        // ---- replay SPT steps (high t -> low t) and store vtrace ----
        #pragma unroll
        for (int i = SPT - 1; i >= 0; --i) {
            float4 vt;
            vt.x = fmaf(bv[i].x, carry.x, av[i].x);
            vt.y = fmaf(bv[i].y, carry.y, av[i].y);
            vt.z = fmaf(bv[i].z, carry.z, av[i].z);
            vt.w = fmaf(bv[i].w, carry.w, av[i].w);
            __stcs(pvo + i * B4, vt);
            carry = vt;
        }

        // Lowest-t thread's final carry enters the next (lower-t) tile.
        // Written after sync2; next tile's sync1 orders it before reads.
        if (seg == 0) sCarry[col] = carry;

        // step pointers back one tile
        pv  -= TILE * B4;  pr  -= TILE * B4;  ptl -= TILE * B4;
        pbl -= TILE * B4;  pro -= TILE * B4;  pvo -= TILE * B4;
    }
}

// Inputs (metadata order): target_value, rewards, target_log_policy,
// behaviour_log_policy — all fp32 [T, B]. Output: [vtrace | rhos] fp32.
extern "C" void kernel_launch(void* const* d_in, const int* in_sizes, int n_in,
                              void* d_out, int out_size)
{
    const float4* v  = (const float4*)d_in[0];
    const float4* r  = (const float4*)d_in[1];
    const float4* tl = (const float4*)d_in[2];
    const float4* bl = (const float4*)d_in[3];

    float4* vout    = (float4*)d_out;
    float4* rho_out = vout + (size_t)TT * B4;

    vtrace_fused<<<B4 / CPB, NTHR>>>(v, r, tl, bl, vout, rho_out);
}

// round 17
// speedup vs baseline: 1.1543x; 1.1543x over previous
#include <cuda_runtime.h>

#define TT    2048
#define BCOL  8192
#define B4    (BCOL / 4)       // 2048 float4 columns
#define CPB   4                // float4 columns per block
#define SEGS  64               // T-segments per tile
#define SPT   4                // steps per thread (segment length)
#define TILE  (SEGS * SPT)     // 256 T-steps per tile
#define NTILE (TT / TILE)      // 8 tiles
#define NTHR  (SEGS * CPB)     // 256 threads, 8 warps
#define NW    (NTHR / 32)      // 8 warps
#define SEGW  8                // segments per warp
#define GAMMA 0.99f

// Fully fused V-trace (single launch):
//   rho_t = min(1, exp(tl-bl))                              (output)
//   a_t   = v_t + rho_t*(r_t - v_t),  b_t = GAMMA*rho_t     [t==T-1: a=v, b=0]
//   v_t   = a_t + b_t * v_{t+1}   (reverse affine scan)     (output)
// (gamma*v_next cancels exactly in a_t because RHO == CIS == 1.)
//
// R7 measured: 80.4us, DRAM 59.8%, occ 32.6%, 74 regs -> 3 CTA/SM -> 444
// slots vs 512 CTAs -> 68-CTA latency-bound second wave (~13us tail).
// R9-R17 candidate: __launch_bounds__(256,4) -> 592 slots, ONE wave; bv[]
// register array eliminated (b recomputed as GAMMA*rho on use, t==T-1
// handled by zeroing rho in-register AFTER the rho store) so the 64-reg
// cap holds without spills.
__global__ void __launch_bounds__(NTHR, 4) vtrace_fused(
    const float4* __restrict__ v,  const float4* __restrict__ r,
    const float4* __restrict__ tl, const float4* __restrict__ bl,
    float4* __restrict__ vout, float4* __restrict__ rho_out)
{
    __shared__ float4 sWA[NW][CPB];     // per-warp aggregate A
    __shared__ float4 sWP[NW][CPB];     // per-warp aggregate P
    __shared__ float4 sCarry[CPB];      // carry entering next (lower-t) tile

    const int tid  = threadIdx.x;
    const int col  = tid & (CPB - 1);
    const int seg  = tid >> 2;
    const int wid  = tid >> 5;
    const int sl   = (tid & 31) >> 2;   // segment-local id within warp (0..7)
    const int colg = blockIdx.x * CPB + col;

    if (tid < CPB) sCarry[tid] = make_float4(0.f, 0.f, 0.f, 0.f);
    // First-tile read of sCarry is ordered by sync1 below.

    // Running pointers for this thread's segment in the LAST tile; walk
    // backwards by TILE rows per tile iteration.
    const int base0 = ((NTILE - 1) * TILE + seg * SPT) * B4 + colg;
    const float4* pv  = v       + base0;
    const float4* pr  = r       + base0;
    const float4* ptl = tl      + base0;
    const float4* pbl = bl      + base0;
    float4*       pro = rho_out + base0;
    float4*       pvo = vout    + base0;

    const bool own_last = (seg == SEGS - 1);   // owns t==TT-1 in last tile

    for (int tt = NTILE - 1; tt >= 0; --tt) {
        float4 av[SPT];
        float4 rv[SPT];                 // rho; b_t = GAMMA*rv on the fly

        // ---- phase A: policy loads (8 LDG.128), rho, rho store ----
        {
            float4 t4[SPT], b4[SPT];
            #pragma unroll
            for (int i = 0; i < SPT; ++i) {
                t4[i] = __ldcs(ptl + i * B4);
                b4[i] = __ldcs(pbl + i * B4);
            }
            #pragma unroll
            for (int i = 0; i < SPT; ++i) {
                rv[i].x = fminf(1.f, __expf(t4[i].x - b4[i].x));
                rv[i].y = fminf(1.f, __expf(t4[i].y - b4[i].y));
                rv[i].z = fminf(1.f, __expf(t4[i].z - b4[i].z));
                rv[i].w = fminf(1.f, __expf(t4[i].w - b4[i].w));
                __stcs(pro + i * B4, rv[i]);
            }
        }

        // ---- phase B: value loads (8 LDG.128), build a ----
        {
            float4 vv[SPT], rr[SPT];
            #pragma unroll
            for (int i = 0; i < SPT; ++i) {
                vv[i] = __ldcs(pv + i * B4);
                rr[i] = __ldcs(pr + i * B4);
            }
            #pragma unroll
            for (int i = 0; i < SPT; ++i) {
                av[i].x = fmaf(rv[i].x, rr[i].x - vv[i].x, vv[i].x);
                av[i].y = fmaf(rv[i].y, rr[i].y - vv[i].y, vv[i].y);
                av[i].z = fmaf(rv[i].z, rr[i].z - vv[i].z, vv[i].z);
                av[i].w = fmaf(rv[i].w, rr[i].w - vv[i].w, vv[i].w);
            }
            if (tt == NTILE - 1 && own_last) {
                // t==TT-1: a=v, b=0. rho already stored; zero the register
                // copy so b = GAMMA*rv = 0 everywhere below.
                av[SPT - 1] = vv[SPT - 1];
                rv[SPT - 1] = make_float4(0.f, 0.f, 0.f, 0.f);
            }
        }

        // ---- per-thread segment aggregate K = M_lo o ... o M_hi ----
        float4 KA = make_float4(0.f, 0.f, 0.f, 0.f);
        float4 KP = make_float4(1.f, 1.f, 1.f, 1.f);
        #pragma unroll
        for (int i = SPT - 1; i >= 0; --i) {
            const float bx = GAMMA * rv[i].x, by = GAMMA * rv[i].y;
            const float bz = GAMMA * rv[i].z, bw = GAMMA * rv[i].w;
            KA.x = fmaf(bx, KA.x, av[i].x);
            KA.y = fmaf(by, KA.y, av[i].y);
            KA.z = fmaf(bz, KA.z, av[i].z);
            KA.w = fmaf(bw, KA.w, av[i].w);
            KP.x *= bx;  KP.y *= by;  KP.z *= bz;  KP.w *= bw;
        }

        // ---- intra-warp suffix scan over 8 segments (shuffles, no BAR) ----
        #pragma unroll
        for (int d = 1; d < SEGW; d <<= 1) {
            const int sh = 4 * d;
            float4 pA, pP;
            pA.x = __shfl_down_sync(0xffffffffu, KA.x, sh);
            pA.y = __shfl_down_sync(0xffffffffu, KA.y, sh);
            pA.z = __shfl_down_sync(0xffffffffu, KA.z, sh);
            pA.w = __shfl_down_sync(0xffffffffu, KA.w, sh);
            pP.x = __shfl_down_sync(0xffffffffu, KP.x, sh);
            pP.y = __shfl_down_sync(0xffffffffu, KP.y, sh);
            pP.z = __shfl_down_sync(0xffffffffu, KP.z, sh);
            pP.w = __shfl_down_sync(0xffffffffu, KP.w, sh);
            if (sl + d < SEGW) {
                KA.x = fmaf(KP.x, pA.x, KA.x);
                KA.y = fmaf(KP.y, pA.y, KA.y);
                KA.z = fmaf(KP.z, pA.z, KA.z);
                KA.w = fmaf(KP.w, pA.w, KA.w);
                KP.x *= pP.x;  KP.y *= pP.y;
                KP.z *= pP.z;  KP.w *= pP.w;
            }
        }

        // nK = suffix aggregate of the segment just above mine (within warp)
        float4 nKA, nKP;
        nKA.x = __shfl_down_sync(0xffffffffu, KA.x, 4);
        nKA.y = __shfl_down_sync(0xffffffffu, KA.y, 4);
        nKA.z = __shfl_down_sync(0xffffffffu, KA.z, 4);
        nKA.w = __shfl_down_sync(0xffffffffu, KA.w, 4);
        nKP.x = __shfl_down_sync(0xffffffffu, KP.x, 4);
        nKP.y = __shfl_down_sync(0xffffffffu, KP.y, 4);
        nKP.z = __shfl_down_sync(0xffffffffu, KP.z, 4);
        nKP.w = __shfl_down_sync(0xffffffffu, KP.w, 4);

        // ---- publish warp aggregates (K at sl==0 spans the whole warp) ----
        if (sl == 0) {
            sWA[wid][col] = KA;
            sWP[wid][col] = KP;
        }
        __syncthreads();    // sync1: aggregates visible; orders sCarry w->r

        // ---- carry entering my warp: C = (W_{wid+1} o..o W_{NW-1})(tc) ----
        float4 C = sCarry[col];
        #pragma unroll
        for (int w2 = NW - 1; w2 >= 1; --w2) {  // innermost (highest t) first
            if (w2 > wid) {
                const float4 A = sWA[w2][col];
                const float4 P = sWP[w2][col];
                C.x = fmaf(P.x, C.x, A.x);
                C.y = fmaf(P.y, C.y, A.y);
                C.z = fmaf(P.z, C.z, A.z);
                C.w = fmaf(P.w, C.w, A.w);
            }
        }

        // ---- carry entering my segment ----
        float4 carry;
        if (sl == SEGW - 1) {
            carry = C;
        } else {
            carry.x = fmaf(nKP.x, C.x, nKA.x);
            carry.y = fmaf(nKP.y, C.y, nKA.y);
            carry.z = fmaf(nKP.z, C.z, nKA.z);
            carry.w = fmaf(nKP.w, C.w, nKA.w);
        }
        __syncthreads();    // sync2: all smem reads done before any rewrite

        // ---- replay SPT steps (high t -> low t) and store vtrace ----
        #pragma unroll
        for (int i = SPT - 1; i >= 0; --i) {
            // vt = a + rho*(GAMMA*carry)
            const float gcx = GAMMA * carry.x, gcy = GAMMA * carry.y;
            const float gcz = GAMMA * carry.z, gcw = GAMMA * carry.w;
            float4 vt;
            vt.x = fmaf(rv[i].x, gcx, av[i].x);
            vt.y = fmaf(rv[i].y, gcy, av[i].y);
            vt.z = fmaf(rv[i].z, gcz, av[i].z);
            vt.w = fmaf(rv[i].w, gcw, av[i].w);
            __stcs(pvo + i * B4, vt);
            carry = vt;
        }

        // Lowest-t thread's final carry enters the next (lower-t) tile.
        // Written after sync2; next tile's sync1 orders it before reads.
        if (seg == 0) sCarry[col] = carry;

        // step pointers back one tile
        pv  -= TILE * B4;  pr  -= TILE * B4;  ptl -= TILE * B4;
        pbl -= TILE * B4;  pro -= TILE * B4;  pvo -= TILE * B4;
    }
}

// Inputs (metadata order): target_value, rewards, target_log_policy,
// behaviour_log_policy — all fp32 [T, B]. Output: [vtrace | rhos] fp32.
extern "C" void kernel_launch(void* const* d_in, const int* in_sizes, int n_in,
                              void* d_out, int out_size)
{
    const float4* v  = (const float4*)d_in[0];
    const float4* r  = (const float4*)d_in[1];
    const float4* tl = (const float4*)d_in[2];
    const float4* bl = (const float4*)d_in[3];

    float4* vout    = (float4*)d_out;
    float4* rho_out = vout + (size_t)TT * B4;

    vtrace_fused<<<B4 / CPB, NTHR>>>(v, r, tl, bl, vout, rho_out);
}